// round 11
// baseline (speedup 1.0000x reference)
#include <cuda_runtime.h>
#include <cstdint>

#define B_ 4
#define H_ 16
#define S_ 1024
#define D_ 64

#define KEEP_THRESH 0xE6666600u   // bits < thresh  <=>  uniform < 0.9f (verified)

// ---------------------------------------------------------------------------
// add via IMAD with runtime-opaque multiplier (==1) so ptxas cannot fold it
// back to IADD3; lands on the fma pipe, freeing the alu pipe for SHF/LOP3.
// ---------------------------------------------------------------------------
__device__ __forceinline__ uint32_t addm(uint32_t a, uint32_t one, uint32_t b) {
    uint32_t r;
    asm("mad.lo.u32 %0, %1, %2, %3;" : "=r"(r) : "r"(a), "r"(one), "r"(b));
    return r;
}

// ---------------------------------------------------------------------------
// Threefry-2x32 specialized for key (0,42): keep bit for counter (0,c).
// Bit-exact vs JAX partitionable path (verified rel_err 6.4e-8 / 4.1e-5).
// ---------------------------------------------------------------------------
__device__ __forceinline__ uint32_t tf_keep(uint32_t ctr, uint32_t one) {
    const uint32_t KS2 = 0x1BD11BDAu ^ 42u;
    uint32_t x0 = 0u, x1 = ctr + 42u;
#define TF_R(r) { x0 = addm(x0, one, x1); x1 = __funnelshift_l(x1, x1, (r)); x1 ^= x0; }
    TF_R(13) TF_R(15) TF_R(26) TF_R(6)
    x0 = addm(x0, one, 42u);  x1 = addm(x1, one, KS2 + 1u);
    TF_R(17) TF_R(29) TF_R(16) TF_R(24)
    x0 = addm(x0, one, KS2);  x1 = addm(x1, one, 2u);
    TF_R(13) TF_R(15) TF_R(26) TF_R(6)
    /* x0 += 0 */             x1 = addm(x1, one, 45u);
    TF_R(17) TF_R(29) TF_R(16) TF_R(24)
    x0 = addm(x0, one, 42u);  x1 = addm(x1, one, KS2 + 4u);
    TF_R(13) TF_R(15) TF_R(26) TF_R(6)
    x0 = addm(x0, one, KS2);  x1 = addm(x1, one, 5u);
#undef TF_R
    return ((x0 ^ x1) < KEEP_THRESH) ? 1u : 0u;
}

// ---------------------------------------------------------------------------
// bf16 helpers
// ---------------------------------------------------------------------------
__device__ __forceinline__ uint32_t pack2(float lo, float hi) {
    uint32_t r;
    asm("cvt.rn.bf16x2.f32 %0, %1, %2;" : "=r"(r) : "f"(hi), "f"(lo));
    return r;
}
__device__ __forceinline__ float blo(uint32_t w) { return __uint_as_float(w << 16); }
__device__ __forceinline__ float bhi(uint32_t w) { return __uint_as_float(w & 0xffff0000u); }
__device__ __forceinline__ void split2(float a, float b, uint32_t& h, uint32_t& l) {
    h = pack2(a, b);
    l = pack2(a - blo(h), b - bhi(h));
}

// d += A(bf16) * B(bf16), m16n8k16
__device__ __forceinline__ void mma16(float d[4], const uint32_t a[4],
                                      uint32_t b0, uint32_t b1) {
    asm volatile(
        "mma.sync.aligned.m16n8k16.row.col.f32.bf16.bf16.f32 "
        "{%0,%1,%2,%3}, {%4,%5,%6,%7}, {%8,%9}, {%0,%1,%2,%3};"
        : "+f"(d[0]), "+f"(d[1]), "+f"(d[2]), "+f"(d[3])
        : "r"(a[0]), "r"(a[1]), "r"(a[2]), "r"(a[3]), "r"(b0), "r"(b1));
}

__device__ __forceinline__ void ldm_x4(uint32_t r[4], uint32_t addr) {
    asm volatile("ldmatrix.sync.aligned.m8n8.x4.shared.b16 {%0,%1,%2,%3}, [%4];"
                 : "=r"(r[0]), "=r"(r[1]), "=r"(r[2]), "=r"(r[3]) : "r"(addr));
}

__device__ __forceinline__ void cp16(uint32_t saddr, const float* g) {
    asm volatile("cp.async.cg.shared.global [%0], [%1], 16;"
                 :: "r"(saddr), "l"(g));
}

#define PW 36   // bf16x2 word stride: 144 B/row
#define ST 68   // fp32 staging word stride: 272 B/row

// word offsets (P lives in registers; staging holds next tile's raw fp32 K/V)
#define W_QH 0
#define W_QL (128 * PW)
#define W_KH (2 * 128 * PW)
#define W_KL (W_KH + 64 * PW)
#define W_VH (W_KL + 64 * PW)
#define W_VL (W_VH + 64 * PW)
#define W_SK (W_VL + 64 * PW)            // 18432
#define W_SV (W_SK + 64 * ST)            // +4352
#define W_TOT (W_SV + 64 * ST)           // 27136 words = 108544 B -> 2 CTAs/SM

// ---------------------------------------------------------------------------
__global__ void __launch_bounds__(256, 2)
attn_kernel(const float* __restrict__ Q, const float* __restrict__ K,
            const float* __restrict__ V, const uint32_t* __restrict__ scale_ptr,
            float* __restrict__ O) {
    extern __shared__ uint32_t smw[];

    const int tid  = threadIdx.x;
    const int warp = tid >> 5;           // 0..7, owns rows [16w, 16w+16)
    const int lane = tid & 31;
    const int gid  = lane >> 2;          // 0..7
    const int tig  = lane & 3;           // 0..3
    const int bh   = blockIdx.y;
    const int qb   = blockIdx.x << 7;
    const int r0   = warp * 16 + gid;

    uint32_t sw = *scale_ptr;
    float scale = (sw & 0x7f800000u) ? __uint_as_float(sw) : (float)(int)sw;
    const uint32_t one = (sw >> 31) + 1u;   // ==1 at runtime, opaque to ptxas

    // per-lane ldmatrix base addresses (byte, shared space)
    const uint32_t sb = (uint32_t)__cvta_generic_to_shared(smw);
    const uint32_t laneA = (uint32_t)((lane & 15) * PW + ((lane & 16) ? 4 : 0));
    const uint32_t laneBK = (uint32_t)(((lane < 16) ? W_KH : W_KL)
                                       + (lane & 7) * PW + ((lane & 8) ? 4 : 0));
    const uint32_t laneBV = (uint32_t)(((lane < 16) ? W_VH : W_VL)
                                       + (lane & 7) * PW + ((lane & 8) ? 4 : 0));
    const uint32_t aQH = sb + 4u * (W_QH + (uint32_t)(warp * 16) * PW + laneA);
    const uint32_t aQL = sb + 4u * (W_QL + (uint32_t)(warp * 16) * PW + laneA);
    const uint32_t aK  = sb + 4u * laneBK;
    const uint32_t aV  = sb + 4u * laneBV;

    // global bit-index base for this lane's dropout rows (row r0 and r0+8)
    const uint32_t bit_base =
        ((uint32_t)(bh * S_ + qb + r0) << 10) + 2u * (uint32_t)tig;

    const float* Kbh = K + (size_t)bh * S_ * D_;
    const float* Vbh = V + (size_t)bh * S_ * D_;

    // ---- prefetch tile 0 K/V (raw fp32) into staging ----
#pragma unroll
    for (int i = 0; i < 4; i++) {
        int lin = tid + (i << 8);                // 0..1023
        int r = lin >> 4, sg = (lin & 15) << 2;  // row, float-offset
        cp16(sb + 4u * (uint32_t)(W_SK + r * ST + sg), Kbh + r * 64 + sg);
        cp16(sb + 4u * (uint32_t)(W_SV + r * ST + sg), Vbh + r * 64 + sg);
    }
    asm volatile("cp.async.commit_group;" ::: "memory");

    // ---- Q prologue: stage scaled hi/lo bf16x2 words into smem ----
    {
        int r = tid >> 1, half = (tid & 1) * 32;
        const float4* Qp = reinterpret_cast<const float4*>(
            Q + ((size_t)bh * S_ + qb + r) * D_ + half);
        int wb = r * PW + (half >> 1);
#pragma unroll
        for (int i = 0; i < 8; i++) {
            float4 v = Qp[i];
            uint32_t h0, l0, h1, l1;
            split2(v.x * scale, v.y * scale, h0, l0);
            split2(v.z * scale, v.w * scale, h1, l1);
            smw[W_QH + wb + 2 * i]     = h0;
            smw[W_QH + wb + 2 * i + 1] = h1;
            smw[W_QL + wb + 2 * i]     = l0;
            smw[W_QL + wb + 2 * i + 1] = l1;
        }
    }

    float m_[2], l_[2];
    float o[8][4];
    m_[0] = m_[1] = -1e30f;
    l_[0] = l_[1] = 0.f;
#pragma unroll
    for (int n = 0; n < 8; n++)
#pragma unroll
        for (int c = 0; c < 4; c++) o[n][c] = 0.f;

#pragma unroll 1
    for (int t = 0; t < 16; t++) {
        asm volatile("cp.async.wait_group 0;" ::: "memory");
        __syncthreads();                 // staging ready; prev readers done

        // ---- K split: staging fp32 -> bf16 hi/lo (LDS, no LDG stall) ----
        {
            int r = tid >> 2, qv = (tid & 3) << 4;
            const float4* Kst = reinterpret_cast<const float4*>(
                reinterpret_cast<const float*>(smw) + W_SK + r * ST + qv);
            uint32_t kh[8], kl[8];
#pragma unroll
            for (int i = 0; i < 4; i++) {
                float4 v = Kst[i];
                split2(v.x, v.y, kh[2 * i],     kl[2 * i]);
                split2(v.z, v.w, kh[2 * i + 1], kl[2 * i + 1]);
            }
            int wb = r * PW + (qv >> 1);
            *reinterpret_cast<uint4*>(smw + W_KH + wb) =
                make_uint4(kh[0], kh[1], kh[2], kh[3]);
            *reinterpret_cast<uint4*>(smw + W_KH + wb + 4) =
                make_uint4(kh[4], kh[5], kh[6], kh[7]);
            *reinterpret_cast<uint4*>(smw + W_KL + wb) =
                make_uint4(kl[0], kl[1], kl[2], kl[3]);
            *reinterpret_cast<uint4*>(smw + W_KL + wb + 4) =
                make_uint4(kl[4], kl[5], kl[6], kl[7]);
        }

        // ---- V split: staging fp32 -> transposed bf16 hi/lo ----
        {
            int kp = tid & 31, db = (tid >> 5) << 3;
            const float* s0 = reinterpret_cast<const float*>(smw)
                              + W_SV + (2 * kp) * ST + db;
            float4 a0 = reinterpret_cast<const float4*>(s0)[0];
            float4 a1 = reinterpret_cast<const float4*>(s0)[1];
            float4 b0 = reinterpret_cast<const float4*>(s0 + ST)[0];
            float4 b1 = reinterpret_cast<const float4*>(s0 + ST)[1];
            float fa[8] = {a0.x, a0.y, a0.z, a0.w, a1.x, a1.y, a1.z, a1.w};
            float fb[8] = {b0.x, b0.y, b0.z, b0.w, b1.x, b1.y, b1.z, b1.w};
#pragma unroll
            for (int i = 0; i < 8; i++) {
                uint32_t h, l;
                split2(fa[i], fb[i], h, l);    // lo=key 2kp, hi=key 2kp+1
                smw[W_VH + (db + i) * PW + kp] = h;
                smw[W_VL + (db + i) * PW + kp] = l;
            }
        }
        __syncthreads();                 // bf16 tiles ready; staging free

        // ---- prefetch tile t+1 into staging (overlaps QK/threefry/PV) ----
        if (t < 15) {
            const float* Kt = Kbh + (t + 1) * 64 * D_;
            const float* Vt = Vbh + (t + 1) * 64 * D_;
#pragma unroll
            for (int i = 0; i < 4; i++) {
                int lin = tid + (i << 8);
                int r = lin >> 4, sg = (lin & 15) << 2;
                cp16(sb + 4u * (uint32_t)(W_SK + r * ST + sg), Kt + r * 64 + sg);
                cp16(sb + 4u * (uint32_t)(W_SV + r * ST + sg), Vt + r * 64 + sg);
            }
        }
        asm volatile("cp.async.commit_group;" ::: "memory");

        // ---- QK: 3-term bf16, Q via ldmatrix, K via ldmatrix.x4 ----
        float s[8][4];
#pragma unroll
        for (int n = 0; n < 8; n++)
#pragma unroll
            for (int c = 0; c < 4; c++) s[n][c] = 0.f;

#pragma unroll
        for (int ks = 0; ks < 4; ks++) {
            uint32_t qh[4], ql[4];
            ldm_x4(qh, aQH + ks * 32u);
            ldm_x4(ql, aQL + ks * 32u);
#pragma unroll
            for (int n = 0; n < 8; n++) {
                uint32_t kb[4];
                ldm_x4(kb, aK + 4u * (uint32_t)(n * 8 * PW + ks * 8));
                mma16(s[n], qh, kb[0], kb[1]);
                mma16(s[n], ql, kb[0], kb[1]);
                mma16(s[n], qh, kb[2], kb[3]);
            }
        }

        // ---- fused dropout mask: 32 threefry evals (fills HMMA latency) ----
        uint32_t lm0 = 0u, lm1 = 0u;
        {
            uint32_t c0 = bit_base + (uint32_t)(t * 64);
            uint32_t c1 = c0 + (8u << 10);
#pragma unroll 1
            for (int j = 0; j < 8; j++) {
                uint32_t cj0 = c0 + 8u * (uint32_t)j;
                uint32_t cj1 = c1 + 8u * (uint32_t)j;
                lm0 |= tf_keep(cj0, one)      << (2 * j);
                lm0 |= tf_keep(cj0 + 1u, one) << (2 * j + 1);
                lm1 |= tf_keep(cj1, one)      << (2 * j);
                lm1 |= tf_keep(cj1 + 1u, one) << (2 * j + 1);
            }
        }

        // ---- online softmax (row lives on a lane quad) ----
#pragma unroll
        for (int h = 0; h < 2; h++) {
            float mx = -1e30f;
#pragma unroll
            for (int n = 0; n < 8; n++)
                mx = fmaxf(mx, fmaxf(s[n][2 * h], s[n][2 * h + 1]));
            mx = fmaxf(mx, __shfl_xor_sync(0xffffffffu, mx, 1));
            mx = fmaxf(mx, __shfl_xor_sync(0xffffffffu, mx, 2));
            float mnew = fmaxf(m_[h], mx);
            float corr = __expf(m_[h] - mnew);
            m_[h] = mnew;
            float sum = 0.f;
#pragma unroll
            for (int n = 0; n < 8; n++) {
                float e0 = __expf(s[n][2 * h] - mnew);
                float e1 = __expf(s[n][2 * h + 1] - mnew);
                s[n][2 * h] = e0;
                s[n][2 * h + 1] = e1;
                sum += e0 + e1;
            }
            sum += __shfl_xor_sync(0xffffffffu, sum, 1);
            sum += __shfl_xor_sync(0xffffffffu, sum, 2);
            l_[h] = l_[h] * corr + sum;
#pragma unroll
            for (int n = 0; n < 8; n++) {
                o[n][2 * h] *= corr;
                o[n][2 * h + 1] *= corr;
            }
        }

        // ---- PV: dropout + pack P chunk in regs, V via ldmatrix.x4 ----
#pragma unroll
        for (int ks = 0; ks < 4; ks++) {
            uint32_t aph[4], apl[4];
#pragma unroll
            for (int q = 0; q < 4; q++) {          // q = 2*(n-2ks) + h
                int n = 2 * ks + (q >> 1);
                int h = q & 1;
                uint32_t lm = h ? lm1 : lm0;
                float p0 = ((lm >> (2 * n)) & 1u)     ? s[n][2 * h] : 0.f;
                float p1 = ((lm >> (2 * n + 1)) & 1u) ? s[n][2 * h + 1] : 0.f;
                int ar = (q >> 1) * 2 + h;         // n-low: a0/a1, n-high: a2/a3
                split2(p0, p1, aph[ar], apl[ar]);
            }
#pragma unroll
            for (int n = 0; n < 8; n++) {
                uint32_t vb[4];
                ldm_x4(vb, aV + 4u * (uint32_t)(n * 8 * PW + ks * 8));
                mma16(o[n], aph, vb[0], vb[1]);
                mma16(o[n], aph, vb[2], vb[3]);
                mma16(o[n], apl, vb[0], vb[1]);
            }
        }
    }

    // ---- epilogue: O / (0.9 * l), write global ----
#pragma unroll
    for (int h = 0; h < 2; h++) {
        float inv = 1.f / (0.9f * l_[h]);
        int row = qb + r0 + h * 8;
        float* Op = O + ((size_t)bh * S_ + row) * D_;
#pragma unroll
        for (int n = 0; n < 8; n++) {
            float2 v;
            v.x = o[n][2 * h] * inv;
            v.y = o[n][2 * h + 1] * inv;
            *reinterpret_cast<float2*>(Op + n * 8 + 2 * tig) = v;
        }
    }
}

// ---------------------------------------------------------------------------
extern "C" void kernel_launch(void* const* d_in, const int* in_sizes, int n_in,
                              void* d_out, int out_size) {
    (void)in_sizes; (void)n_in; (void)out_size;
    const float*    Q  = (const float*)d_in[0];
    const float*    K  = (const float*)d_in[1];
    const float*    V  = (const float*)d_in[2];
    const uint32_t* SC = (const uint32_t*)d_in[3];
    float*          O  = (float*)d_out;

    const int smem = W_TOT * (int)sizeof(uint32_t);   // 108544 B
    cudaFuncSetAttribute(attn_kernel,
                         cudaFuncAttributeMaxDynamicSharedMemorySize, smem);
    dim3 grid(S_ / 128, B_ * H_);
    attn_kernel<<<grid, 256, smem>>>(Q, K, V, SC, O);
}

// round 12
// speedup vs baseline: 1.0476x; 1.0476x over previous
#include <cuda_runtime.h>
#include <cstdint>

#define B_ 4
#define H_ 16
#define S_ 1024
#define D_ 64

#define KEEP_THRESH 0xE6666600u   // bits < thresh  <=>  uniform < 0.9f (verified)

// ---------------------------------------------------------------------------
// Threefry-2x32 specialized for key (0,42): keep bit for counter (0,c).
// Bit-exact vs JAX partitionable path (verified across R2..R10).
// ---------------------------------------------------------------------------
__device__ __forceinline__ uint32_t tf_keep(uint32_t ctr) {
    const uint32_t KS2 = 0x1BD11BDAu ^ 42u;
    uint32_t x0 = 0u, x1 = ctr + 42u;
#define TF_R(r) { x0 += x1; x1 = __funnelshift_l(x1, x1, (r)); x1 ^= x0; }
    TF_R(13) TF_R(15) TF_R(26) TF_R(6)
    x0 += 42u;  x1 += KS2 + 1u;
    TF_R(17) TF_R(29) TF_R(16) TF_R(24)
    x0 += KS2;  x1 += 2u;
    TF_R(13) TF_R(15) TF_R(26) TF_R(6)
    /* x0 += 0 */ x1 += 45u;
    TF_R(17) TF_R(29) TF_R(16) TF_R(24)
    x0 += 42u;  x1 += KS2 + 4u;
    TF_R(13) TF_R(15) TF_R(26) TF_R(6)
    x0 += KS2;  x1 += 5u;
#undef TF_R
    return ((x0 ^ x1) < KEEP_THRESH) ? 1u : 0u;
}

// ---------------------------------------------------------------------------
// bf16 helpers
// ---------------------------------------------------------------------------
__device__ __forceinline__ uint32_t pack2(float lo, float hi) {
    uint32_t r;
    asm("cvt.rn.bf16x2.f32 %0, %1, %2;" : "=r"(r) : "f"(hi), "f"(lo));
    return r;
}
__device__ __forceinline__ float blo(uint32_t w) { return __uint_as_float(w << 16); }
__device__ __forceinline__ float bhi(uint32_t w) { return __uint_as_float(w & 0xffff0000u); }
__device__ __forceinline__ void split2(float a, float b, uint32_t& h, uint32_t& l) {
    h = pack2(a, b);
    l = pack2(a - blo(h), b - bhi(h));
}

// d += A(bf16) * B(bf16), m16n8k16
__device__ __forceinline__ void mma16(float d[4], const uint32_t a[4],
                                      uint32_t b0, uint32_t b1) {
    asm volatile(
        "mma.sync.aligned.m16n8k16.row.col.f32.bf16.bf16.f32 "
        "{%0,%1,%2,%3}, {%4,%5,%6,%7}, {%8,%9}, {%0,%1,%2,%3};"
        : "+f"(d[0]), "+f"(d[1]), "+f"(d[2]), "+f"(d[3])
        : "r"(a[0]), "r"(a[1]), "r"(a[2]), "r"(a[3]), "r"(b0), "r"(b1));
}

__device__ __forceinline__ void ldm_x4(uint32_t r[4], uint32_t addr) {
    asm volatile("ldmatrix.sync.aligned.m8n8.x4.shared.b16 {%0,%1,%2,%3}, [%4];"
                 : "=r"(r[0]), "=r"(r[1]), "=r"(r[2]), "=r"(r[3]) : "r"(addr));
}

__device__ __forceinline__ void cp16(uint32_t saddr, const float* g) {
    asm volatile("cp.async.cg.shared.global [%0], [%1], 16;"
                 :: "r"(saddr), "l"(g));
}

#define PW 36   // bf16x2 word stride: 144 B/row
#define ST 68   // fp32 staging word stride: 272 B/row

// word offsets
#define W_QH 0
#define W_QL (128 * PW)
#define W_KH (2 * 128 * PW)
#define W_KL (W_KH + 64 * PW)
#define W_VH (W_KL + 64 * PW)
#define W_VL (W_VH + 64 * PW)
#define W_SK (W_VL + 64 * PW)            // 18432 (fp32 staging, tile t+1)
#define W_SV (W_SK + 64 * ST)
#define W_MR (W_SV + 64 * ST)            // 27136 mask ring: 2 pages x 256 words
#define W_TOT (W_MR + 512)               // 27648 words = 110592 B

// ---------------------------------------------------------------------------
__global__ void __launch_bounds__(512, 1)
attn_kernel(const float* __restrict__ Q, const float* __restrict__ K,
            const float* __restrict__ V, const uint32_t* __restrict__ scale_ptr,
            float* __restrict__ O) {
    extern __shared__ uint32_t smw[];

    const int tid  = threadIdx.x;
    const int warp = tid >> 5;
    const int lane = tid & 31;
    const int gid  = lane >> 2;          // 0..7
    const int tig  = lane & 3;           // 0..3
    const int bh   = blockIdx.y;
    const int qb   = blockIdx.x << 7;
    const bool is_attn = warp < 8;       // warps 0-7 attention, 8-15 threefry
    const int r0   = (warp & 7) * 16 + gid;

    // mask-producer thread coords (warps 8-15): 256 threads -> 256 ring words
    const int mm    = tid - 256;         // 0..255 for mask warps
    const int mrow  = mm >> 1;           // 0..127
    const int mhalf = mm & 1;            // word half (cols 0-31 / 32-63)

    uint32_t sw = *scale_ptr;
    float scale = (sw & 0x7f800000u) ? __uint_as_float(sw) : (float)(int)sw;

    // per-lane ldmatrix base addresses (byte, shared space)
    const uint32_t sb = (uint32_t)__cvta_generic_to_shared(smw);
    const uint32_t laneA = (uint32_t)((lane & 15) * PW + ((lane & 16) ? 4 : 0));
    const uint32_t laneBK = (uint32_t)(((lane < 16) ? W_KH : W_KL)
                                       + (lane & 7) * PW + ((lane & 8) ? 4 : 0));
    const uint32_t laneBV = (uint32_t)(((lane < 16) ? W_VH : W_VL)
                                       + (lane & 7) * PW + ((lane & 8) ? 4 : 0));
    const uint32_t aQH = sb + 4u * (W_QH + (uint32_t)((warp & 7) * 16) * PW + laneA);
    const uint32_t aQL = sb + 4u * (W_QL + (uint32_t)((warp & 7) * 16) * PW + laneA);
    const uint32_t aK  = sb + 4u * laneBK;
    const uint32_t aV  = sb + 4u * laneBV;

    // threefry counter base for mask threads (row mrow, half mhalf)
    const uint32_t mbase =
        ((uint32_t)(bh * S_ + qb + mrow) << 10) + (uint32_t)(mhalf << 5);

    const float* Kbh = K + (size_t)bh * S_ * D_;
    const float* Vbh = V + (size_t)bh * S_ * D_;

    // ---- prefetch tile 0 K/V (raw fp32) into staging: all 512 threads ----
#pragma unroll
    for (int i = 0; i < 2; i++) {
        int lin = tid + (i << 9);                // 0..1023
        int r = lin >> 4, sg = (lin & 15) << 2;  // row, float offset
        cp16(sb + 4u * (uint32_t)(W_SK + r * ST + sg), Kbh + r * 64 + sg);
        cp16(sb + 4u * (uint32_t)(W_SV + r * ST + sg), Vbh + r * 64 + sg);
    }
    asm volatile("cp.async.commit_group;" ::: "memory");

    // ---- Q prologue: all 512 threads stage scaled hi/lo bf16x2 words ----
    {
        int r = tid >> 2, qtr = (tid & 3) << 4;  // row, float offset (16 floats)
        const float4* Qp = reinterpret_cast<const float4*>(
            Q + ((size_t)bh * S_ + qb + r) * D_ + qtr);
        int wb = r * PW + (qtr >> 1);
#pragma unroll
        for (int i = 0; i < 4; i++) {
            float4 v = Qp[i];
            uint32_t h0, l0, h1, l1;
            split2(v.x * scale, v.y * scale, h0, l0);
            split2(v.z * scale, v.w * scale, h1, l1);
            smw[W_QH + wb + 2 * i]     = h0;
            smw[W_QH + wb + 2 * i + 1] = h1;
            smw[W_QL + wb + 2 * i]     = l0;
            smw[W_QL + wb + 2 * i + 1] = l1;
        }
    }

    // ---- mask prologue: warps 8-15 generate tile 0 into ring page 0 ----
    if (!is_attn) {
        uint32_t base = mbase;                   // tile 0
        uint32_t w = 0u;
#pragma unroll 1
        for (int b = 0; b < 32; b += 4) {
            w |= tf_keep(base + b)      << b;
            w |= tf_keep(base + b + 1u) << (b + 1);
            w |= tf_keep(base + b + 2u) << (b + 2);
            w |= tf_keep(base + b + 3u) << (b + 3);
        }
        smw[W_MR + (mrow << 1) + mhalf] = w;
    }

    float m_[2], l_[2];
    float o[8][4];
    m_[0] = m_[1] = -1e30f;
    l_[0] = l_[1] = 0.f;
#pragma unroll
    for (int n = 0; n < 8; n++)
#pragma unroll
        for (int c = 0; c < 4; c++) o[n][c] = 0.f;

    __syncthreads();

#pragma unroll 1
    for (int t = 0; t < 16; t++) {
        asm volatile("cp.async.wait_group 0;" ::: "memory");
        __syncthreads();                 // staging ready; prev readers done

        // ---- K split (all 512): staging fp32 -> bf16 hi/lo ----
        {
            int r = tid >> 3, sg8 = (tid & 7) << 3;   // row, float offset (8)
            const float4* Kst = reinterpret_cast<const float4*>(
                reinterpret_cast<const float*>(smw) + W_SK + r * ST + sg8);
            float4 v0 = Kst[0], v1 = Kst[1];
            uint32_t kh[4], kl[4];
            split2(v0.x, v0.y, kh[0], kl[0]);
            split2(v0.z, v0.w, kh[1], kl[1]);
            split2(v1.x, v1.y, kh[2], kl[2]);
            split2(v1.z, v1.w, kh[3], kl[3]);
            int wb = r * PW + (sg8 >> 1);
            *reinterpret_cast<uint4*>(smw + W_KH + wb) =
                make_uint4(kh[0], kh[1], kh[2], kh[3]);
            *reinterpret_cast<uint4*>(smw + W_KL + wb) =
                make_uint4(kl[0], kl[1], kl[2], kl[3]);
        }

        // ---- V split (all 512): staging fp32 -> transposed bf16 hi/lo ----
        {
            int kp = tid & 31, db = (tid >> 5) << 2;  // key pair, 4 d-values
            const float* s0 = reinterpret_cast<const float*>(smw)
                              + W_SV + (2 * kp) * ST + db;
            float4 a = *reinterpret_cast<const float4*>(s0);
            float4 b = *reinterpret_cast<const float4*>(s0 + ST);
            float fa[4] = {a.x, a.y, a.z, a.w};
            float fb[4] = {b.x, b.y, b.z, b.w};
#pragma unroll
            for (int i = 0; i < 4; i++) {
                uint32_t h, l;
                split2(fa[i], fb[i], h, l);    // lo=key 2kp, hi=key 2kp+1
                smw[W_VH + (db + i) * PW + kp] = h;
                smw[W_VL + (db + i) * PW + kp] = l;
            }
        }
        __syncthreads();                 // bf16 tiles + ring[t&1] consumable

        // ---- prefetch tile t+1 staging (all 512 threads) ----
        if (t < 15) {
            const float* Kt = Kbh + (t + 1) * 64 * D_;
            const float* Vt = Vbh + (t + 1) * 64 * D_;
#pragma unroll
            for (int i = 0; i < 2; i++) {
                int lin = tid + (i << 9);
                int r = lin >> 4, sg = (lin & 15) << 2;
                cp16(sb + 4u * (uint32_t)(W_SK + r * ST + sg), Kt + r * 64 + sg);
                cp16(sb + 4u * (uint32_t)(W_SV + r * ST + sg), Vt + r * 64 + sg);
            }
        }
        asm volatile("cp.async.commit_group;" ::: "memory");

        if (is_attn) {
            // ---- mask words for this tile from smem ring ----
            uint2 mw[2];
#pragma unroll
            for (int h = 0; h < 2; h++)
                mw[h] = *reinterpret_cast<const uint2*>(
                    smw + W_MR + (t & 1) * 256 + ((r0 + 8 * h) << 1));

            // ---- QK: 3-term bf16, Q/K via ldmatrix ----
            float s[8][4];
#pragma unroll
            for (int n = 0; n < 8; n++)
#pragma unroll
                for (int c = 0; c < 4; c++) s[n][c] = 0.f;

#pragma unroll
            for (int ks = 0; ks < 4; ks++) {
                uint32_t qh[4], ql[4];
                ldm_x4(qh, aQH + ks * 32u);
                ldm_x4(ql, aQL + ks * 32u);
#pragma unroll
                for (int n = 0; n < 8; n++) {
                    uint32_t kb[4];
                    ldm_x4(kb, aK + 4u * (uint32_t)(n * 8 * PW + ks * 8));
                    mma16(s[n], qh, kb[0], kb[1]);
                    mma16(s[n], ql, kb[0], kb[1]);
                    mma16(s[n], qh, kb[2], kb[3]);
                }
            }

            // ---- online softmax (row lives on a lane quad) ----
#pragma unroll
            for (int h = 0; h < 2; h++) {
                float mx = -1e30f;
#pragma unroll
                for (int n = 0; n < 8; n++)
                    mx = fmaxf(mx, fmaxf(s[n][2 * h], s[n][2 * h + 1]));
                mx = fmaxf(mx, __shfl_xor_sync(0xffffffffu, mx, 1));
                mx = fmaxf(mx, __shfl_xor_sync(0xffffffffu, mx, 2));
                float mnew = fmaxf(m_[h], mx);
                float corr = __expf(m_[h] - mnew);
                m_[h] = mnew;
                float sum = 0.f;
#pragma unroll
                for (int n = 0; n < 8; n++) {
                    float e0 = __expf(s[n][2 * h] - mnew);
                    float e1 = __expf(s[n][2 * h + 1] - mnew);
                    s[n][2 * h] = e0;
                    s[n][2 * h + 1] = e1;
                    sum += e0 + e1;
                }
                sum += __shfl_xor_sync(0xffffffffu, sum, 1);
                sum += __shfl_xor_sync(0xffffffffu, sum, 2);
                l_[h] = l_[h] * corr + sum;
#pragma unroll
                for (int n = 0; n < 8; n++) {
                    o[n][2 * h] *= corr;
                    o[n][2 * h + 1] *= corr;
                }
            }

            // ---- PV: dropout + pack P chunk in regs, V via ldmatrix ----
#pragma unroll
            for (int ks = 0; ks < 4; ks++) {
                uint32_t aph[4], apl[4];
#pragma unroll
                for (int q = 0; q < 4; q++) {      // q = 2*(n-2ks) + h
                    int n = 2 * ks + (q >> 1);
                    int h = q & 1;
                    uint32_t word = (n < 4) ? mw[h].x : mw[h].y;
                    int bit0 = (n & 3) * 8 + 2 * tig;
                    float p0 = ((word >> bit0) & 1u) ? s[n][2 * h] : 0.f;
                    float p1 = ((word >> (bit0 + 1)) & 1u) ? s[n][2 * h + 1] : 0.f;
                    int ar = (q >> 1) * 2 + h;
                    split2(p0, p1, aph[ar], apl[ar]);
                }
#pragma unroll
                for (int n = 0; n < 8; n++) {
                    uint32_t vb[4];
                    ldm_x4(vb, aV + 4u * (uint32_t)(n * 8 * PW + ks * 8));
                    mma16(o[n], aph, vb[0], vb[1]);
                    mma16(o[n], aph, vb[2], vb[3]);
                    mma16(o[n], apl, vb[0], vb[1]);
                }
            }
        } else if (t < 15) {
            // ---- mask warps: generate tile t+1 into ring page (t+1)&1 ----
            uint32_t base = mbase + (uint32_t)((t + 1) * 64);
            uint32_t w = 0u;
#pragma unroll 1
            for (int b = 0; b < 32; b += 4) {
                w |= tf_keep(base + b)      << b;
                w |= tf_keep(base + b + 1u) << (b + 1);
                w |= tf_keep(base + b + 2u) << (b + 2);
                w |= tf_keep(base + b + 3u) << (b + 3);
            }
            smw[W_MR + ((t + 1) & 1) * 256 + (mrow << 1) + mhalf] = w;
        }
    }

    // ---- epilogue: O / (0.9 * l), attn warps only ----
    if (is_attn) {
#pragma unroll
        for (int h = 0; h < 2; h++) {
            float inv = 1.f / (0.9f * l_[h]);
            int row = qb + r0 + h * 8;
            float* Op = O + ((size_t)bh * S_ + row) * D_;
#pragma unroll
            for (int n = 0; n < 8; n++) {
                float2 v;
                v.x = o[n][2 * h] * inv;
                v.y = o[n][2 * h + 1] * inv;
                *reinterpret_cast<float2*>(Op + n * 8 + 2 * tig) = v;
            }
        }
    }
}

// ---------------------------------------------------------------------------
extern "C" void kernel_launch(void* const* d_in, const int* in_sizes, int n_in,
                              void* d_out, int out_size) {
    (void)in_sizes; (void)n_in; (void)out_size;
    const float*    Q  = (const float*)d_in[0];
    const float*    K  = (const float*)d_in[1];
    const float*    V  = (const float*)d_in[2];
    const uint32_t* SC = (const uint32_t*)d_in[3];
    float*          O  = (float*)d_out;

    const int smem = W_TOT * (int)sizeof(uint32_t);   // 110592 B
    cudaFuncSetAttribute(attn_kernel,
                         cudaFuncAttributeMaxDynamicSharedMemorySize, smem);
    dim3 grid(S_ / 128, B_ * H_);
    attn_kernel<<<grid, 512, smem>>>(Q, K, V, SC, O);
}

// round 13
// speedup vs baseline: 1.0751x; 1.0262x over previous
#include <cuda_runtime.h>
#include <cstdint>

#define B_ 4
#define H_ 16
#define S_ 1024
#define D_ 64
#define NTOT   ((size_t)B_ * H_ * S_ * S_)
#define NWORDS (NTOT / 32)

#define KEEP_THRESH 0xE6666600u   // bits < thresh  <=>  uniform < 0.9f (verified)

__device__ uint32_t g_mask[NWORDS];   // 8 MB bitmask scratch

// ---------------------------------------------------------------------------
// Threefry-2x32, key (0,42), JAX partitionable path (bit-exact, verified)
// ---------------------------------------------------------------------------
__device__ __forceinline__ void threefry2x32(uint32_t k0, uint32_t k1,
                                             uint32_t& x0, uint32_t& x1) {
    uint32_t ks2 = 0x1BD11BDAu ^ k0 ^ k1;
    x0 += k0; x1 += k1;
#define TF_RND(r) { x0 += x1; x1 = __funnelshift_l(x1, x1, (r)); x1 ^= x0; }
    TF_RND(13) TF_RND(15) TF_RND(26) TF_RND(6)
    x0 += k1;  x1 += ks2 + 1u;
    TF_RND(17) TF_RND(29) TF_RND(16) TF_RND(24)
    x0 += ks2; x1 += k0 + 2u;
    TF_RND(13) TF_RND(15) TF_RND(26) TF_RND(6)
    x0 += k0;  x1 += k1 + 3u;
    TF_RND(17) TF_RND(29) TF_RND(16) TF_RND(24)
    x0 += k1;  x1 += ks2 + 4u;
    TF_RND(13) TF_RND(15) TF_RND(26) TF_RND(6)
    x0 += ks2; x1 += k0 + 5u;
#undef TF_RND
}

__global__ void __launch_bounds__(256) mask_kernel() {
    uint32_t t = blockIdx.x * 256u + threadIdx.x;
    uint32_t base = t * 32u;
    uint32_t w = 0u;
#pragma unroll 4
    for (int b = 0; b < 32; b++) {
        uint32_t x0 = 0u, x1 = base + (uint32_t)b;
        threefry2x32(0u, 42u, x0, x1);
        w |= (((x0 ^ x1) < KEEP_THRESH) ? 1u : 0u) << b;
    }
    g_mask[t] = w;
}

// ---------------------------------------------------------------------------
// bf16 helpers
// ---------------------------------------------------------------------------
__device__ __forceinline__ uint32_t pack2(float lo, float hi) {
    uint32_t r;
    asm("cvt.rn.bf16x2.f32 %0, %1, %2;" : "=r"(r) : "f"(hi), "f"(lo));
    return r;
}
__device__ __forceinline__ float blo(uint32_t w) { return __uint_as_float(w << 16); }
__device__ __forceinline__ float bhi(uint32_t w) { return __uint_as_float(w & 0xffff0000u); }
__device__ __forceinline__ void split2(float a, float b, uint32_t& h, uint32_t& l) {
    h = pack2(a, b);
    l = pack2(a - blo(h), b - bhi(h));
}

// d += A(bf16) * B(bf16), m16n8k16
__device__ __forceinline__ void mma16(float d[4], const uint32_t a[4],
                                      uint32_t b0, uint32_t b1) {
    asm volatile(
        "mma.sync.aligned.m16n8k16.row.col.f32.bf16.bf16.f32 "
        "{%0,%1,%2,%3}, {%4,%5,%6,%7}, {%8,%9}, {%0,%1,%2,%3};"
        : "+f"(d[0]), "+f"(d[1]), "+f"(d[2]), "+f"(d[3])
        : "r"(a[0]), "r"(a[1]), "r"(a[2]), "r"(a[3]), "r"(b0), "r"(b1));
}

__device__ __forceinline__ void ldm_x4(uint32_t r[4], uint32_t addr) {
    asm volatile("ldmatrix.sync.aligned.m8n8.x4.shared.b16 {%0,%1,%2,%3}, [%4];"
                 : "=r"(r[0]), "=r"(r[1]), "=r"(r[2]), "=r"(r[3]) : "r"(addr));
}

__device__ __forceinline__ void cp16(uint32_t saddr, const float* g) {
    asm volatile("cp.async.cg.shared.global [%0], [%1], 16;"
                 :: "r"(saddr), "l"(g));
}

#define PW 36   // bf16x2 word stride: 144 B/row
#define ST 68   // fp32 staging word stride: 272 B/row

// word offsets (P lives in registers; staging holds next tile's raw fp32 K/V)
#define W_QH 0
#define W_QL (128 * PW)
#define W_KH (2 * 128 * PW)
#define W_KL (W_KH + 64 * PW)
#define W_VH (W_KL + 64 * PW)
#define W_VL (W_VH + 64 * PW)
#define W_SK (W_VL + 64 * PW)            // 18432
#define W_SV (W_SK + 64 * ST)            // +4352
#define W_TOT (W_SV + 64 * ST)           // 27136 words = 108544 B -> 2 CTAs/SM

// ---------------------------------------------------------------------------
__global__ void __launch_bounds__(256, 2)
attn_kernel(const float* __restrict__ Q, const float* __restrict__ K,
            const float* __restrict__ V, const uint32_t* __restrict__ scale_ptr,
            float* __restrict__ O) {
    extern __shared__ uint32_t smw[];

    const int tid  = threadIdx.x;
    const int warp = tid >> 5;           // 0..7, owns rows [16w, 16w+16)
    const int lane = tid & 31;
    const int gid  = lane >> 2;          // 0..7
    const int tig  = lane & 3;           // 0..3
    const int bh   = blockIdx.y;
    const int qb   = blockIdx.x << 7;
    const int r0   = warp * 16 + gid;

    uint32_t sw = *scale_ptr;
    float scale = (sw & 0x7f800000u) ? __uint_as_float(sw) : (float)(int)sw;

    // per-lane ldmatrix base addresses (byte, shared space)
    const uint32_t sb = (uint32_t)__cvta_generic_to_shared(smw);
    const uint32_t laneA = (uint32_t)((lane & 15) * PW + ((lane & 16) ? 4 : 0));
    const uint32_t laneBK = (uint32_t)(((lane < 16) ? W_KH : W_KL)
                                       + (lane & 7) * PW + ((lane & 8) ? 4 : 0));
    const uint32_t laneBV = (uint32_t)(((lane < 16) ? W_VH : W_VL)
                                       + (lane & 7) * PW + ((lane & 8) ? 4 : 0));
    const uint32_t aQH = sb + 4u * (W_QH + (uint32_t)(warp * 16) * PW + laneA);
    const uint32_t aQL = sb + 4u * (W_QL + (uint32_t)(warp * 16) * PW + laneA);
    const uint32_t aK  = sb + 4u * laneBK;
    const uint32_t aV  = sb + 4u * laneBV;

    const float* Kbh = K + (size_t)bh * S_ * D_;
    const float* Vbh = V + (size_t)bh * S_ * D_;

    // ---- prefetch tile 0 K/V (raw fp32) into staging ----
#pragma unroll
    for (int i = 0; i < 4; i++) {
        int lin = tid + (i << 8);                // 0..1023
        int r = lin >> 4, sg = (lin & 15) << 2;  // row, float-offset
        cp16(sb + 4u * (uint32_t)(W_SK + r * ST + sg), Kbh + r * 64 + sg);
        cp16(sb + 4u * (uint32_t)(W_SV + r * ST + sg), Vbh + r * 64 + sg);
    }
    asm volatile("cp.async.commit_group;" ::: "memory");

    // ---- Q prologue: stage scaled hi/lo bf16x2 words into smem ----
    {
        int r = tid >> 1, half = (tid & 1) * 32;
        const float4* Qp = reinterpret_cast<const float4*>(
            Q + ((size_t)bh * S_ + qb + r) * D_ + half);
        int wb = r * PW + (half >> 1);
#pragma unroll
        for (int i = 0; i < 8; i++) {
            float4 v = Qp[i];
            uint32_t h0, l0, h1, l1;
            split2(v.x * scale, v.y * scale, h0, l0);
            split2(v.z * scale, v.w * scale, h1, l1);
            smw[W_QH + wb + 2 * i]     = h0;
            smw[W_QH + wb + 2 * i + 1] = h1;
            smw[W_QL + wb + 2 * i]     = l0;
            smw[W_QL + wb + 2 * i + 1] = l1;
        }
    }

    float m_[2], l_[2];
    float o[8][4];
    m_[0] = m_[1] = -1e30f;
    l_[0] = l_[1] = 0.f;
#pragma unroll
    for (int n = 0; n < 8; n++)
#pragma unroll
        for (int c = 0; c < 4; c++) o[n][c] = 0.f;

#pragma unroll 1
    for (int t = 0; t < 16; t++) {
        // ---- prefetch dropout words (LDG, hidden under split + QK) ----
        uint2 mw[2];
#pragma unroll
        for (int h = 0; h < 2; h++) {
            size_t rg = (size_t)(bh * S_ + qb + r0 + 8 * h);
            mw[h] = *reinterpret_cast<const uint2*>(g_mask + (rg << 5) + t * 2);
        }

        asm volatile("cp.async.wait_group 0;" ::: "memory");
        __syncthreads();                 // staging ready; prev readers done

        // ---- K split: staging fp32 -> bf16 hi/lo (LDS, no LDG stall) ----
        {
            int r = tid >> 2, qv = (tid & 3) << 4;
            const float4* Kst = reinterpret_cast<const float4*>(
                reinterpret_cast<const float*>(smw) + W_SK + r * ST + qv);
            uint32_t kh[8], kl[8];
#pragma unroll
            for (int i = 0; i < 4; i++) {
                float4 v = Kst[i];
                split2(v.x, v.y, kh[2 * i],     kl[2 * i]);
                split2(v.z, v.w, kh[2 * i + 1], kl[2 * i + 1]);
            }
            int wb = r * PW + (qv >> 1);
            *reinterpret_cast<uint4*>(smw + W_KH + wb) =
                make_uint4(kh[0], kh[1], kh[2], kh[3]);
            *reinterpret_cast<uint4*>(smw + W_KH + wb + 4) =
                make_uint4(kh[4], kh[5], kh[6], kh[7]);
            *reinterpret_cast<uint4*>(smw + W_KL + wb) =
                make_uint4(kl[0], kl[1], kl[2], kl[3]);
            *reinterpret_cast<uint4*>(smw + W_KL + wb + 4) =
                make_uint4(kl[4], kl[5], kl[6], kl[7]);
        }

        // ---- V split: staging fp32 -> transposed bf16 hi/lo ----
        {
            int kp = tid & 31, db = (tid >> 5) << 3;
            const float* s0 = reinterpret_cast<const float*>(smw)
                              + W_SV + (2 * kp) * ST + db;
            float4 a0 = reinterpret_cast<const float4*>(s0)[0];
            float4 a1 = reinterpret_cast<const float4*>(s0)[1];
            float4 b0 = reinterpret_cast<const float4*>(s0 + ST)[0];
            float4 b1 = reinterpret_cast<const float4*>(s0 + ST)[1];
            float fa[8] = {a0.x, a0.y, a0.z, a0.w, a1.x, a1.y, a1.z, a1.w};
            float fb[8] = {b0.x, b0.y, b0.z, b0.w, b1.x, b1.y, b1.z, b1.w};
#pragma unroll
            for (int i = 0; i < 8; i++) {
                uint32_t h, l;
                split2(fa[i], fb[i], h, l);    // lo=key 2kp, hi=key 2kp+1
                smw[W_VH + (db + i) * PW + kp] = h;
                smw[W_VL + (db + i) * PW + kp] = l;
            }
        }
        __syncthreads();                 // bf16 tiles ready; staging free

        // ---- prefetch tile t+1 into staging (overlaps QK/PV) ----
        if (t < 15) {
            const float* Kt = Kbh + (t + 1) * 64 * D_;
            const float* Vt = Vbh + (t + 1) * 64 * D_;
#pragma unroll
            for (int i = 0; i < 4; i++) {
                int lin = tid + (i << 8);
                int r = lin >> 4, sg = (lin & 15) << 2;
                cp16(sb + 4u * (uint32_t)(W_SK + r * ST + sg), Kt + r * 64 + sg);
                cp16(sb + 4u * (uint32_t)(W_SV + r * ST + sg), Vt + r * 64 + sg);
            }
        }
        asm volatile("cp.async.commit_group;" ::: "memory");

        // ---- QK: 3-term bf16, Q via ldmatrix, K via ldmatrix.x4 ----
        float s[8][4];
#pragma unroll
        for (int n = 0; n < 8; n++)
#pragma unroll
            for (int c = 0; c < 4; c++) s[n][c] = 0.f;

#pragma unroll
        for (int ks = 0; ks < 4; ks++) {
            uint32_t qh[4], ql[4];
            ldm_x4(qh, aQH + ks * 32u);
            ldm_x4(ql, aQL + ks * 32u);
#pragma unroll
            for (int n = 0; n < 8; n++) {
                uint32_t kb[4];
                ldm_x4(kb, aK + 4u * (uint32_t)(n * 8 * PW + ks * 8));
                mma16(s[n], qh, kb[0], kb[1]);
                mma16(s[n], ql, kb[0], kb[1]);
                mma16(s[n], qh, kb[2], kb[3]);
            }
        }

        // ---- online softmax (row lives on a lane quad) ----
#pragma unroll
        for (int h = 0; h < 2; h++) {
            float mx = -1e30f;
#pragma unroll
            for (int n = 0; n < 8; n++)
                mx = fmaxf(mx, fmaxf(s[n][2 * h], s[n][2 * h + 1]));
            mx = fmaxf(mx, __shfl_xor_sync(0xffffffffu, mx, 1));
            mx = fmaxf(mx, __shfl_xor_sync(0xffffffffu, mx, 2));
            float mnew = fmaxf(m_[h], mx);
            float corr = __expf(m_[h] - mnew);
            m_[h] = mnew;
            float sum = 0.f;
#pragma unroll
            for (int n = 0; n < 8; n++) {
                float e0 = __expf(s[n][2 * h] - mnew);
                float e1 = __expf(s[n][2 * h + 1] - mnew);
                s[n][2 * h] = e0;
                s[n][2 * h + 1] = e1;
                sum += e0 + e1;
            }
            sum += __shfl_xor_sync(0xffffffffu, sum, 1);
            sum += __shfl_xor_sync(0xffffffffu, sum, 2);
            l_[h] = l_[h] * corr + sum;
#pragma unroll
            for (int n = 0; n < 8; n++) {
                o[n][2 * h] *= corr;
                o[n][2 * h + 1] *= corr;
            }
        }

        // ---- PV: dropout + pack P chunk in regs, V via ldmatrix.x4 ----
#pragma unroll
        for (int ks = 0; ks < 4; ks++) {
            uint32_t aph[4], apl[4];
#pragma unroll
            for (int q = 0; q < 4; q++) {          // q = 2*(n-2ks) + h
                int n = 2 * ks + (q >> 1);
                int h = q & 1;
                uint32_t word = (n < 4) ? mw[h].x : mw[h].y;
                int bit0 = (n & 3) * 8 + 2 * tig;
                float p0 = ((word >> bit0) & 1u) ? s[n][2 * h] : 0.f;
                float p1 = ((word >> (bit0 + 1)) & 1u) ? s[n][2 * h + 1] : 0.f;
                int ar = (q >> 1) * 2 + h;         // n-low: a0/a1, n-high: a2/a3
                split2(p0, p1, aph[ar], apl[ar]);
            }
#pragma unroll
            for (int n = 0; n < 8; n++) {
                uint32_t vb[4];
                ldm_x4(vb, aV + 4u * (uint32_t)(n * 8 * PW + ks * 8));
                mma16(o[n], aph, vb[0], vb[1]);
                mma16(o[n], aph, vb[2], vb[3]);
                mma16(o[n], apl, vb[0], vb[1]);
            }
        }
    }

    // ---- epilogue: O / (0.9 * l), write global ----
#pragma unroll
    for (int h = 0; h < 2; h++) {
        float inv = 1.f / (0.9f * l_[h]);
        int row = qb + r0 + h * 8;
        float* Op = O + ((size_t)bh * S_ + row) * D_;
#pragma unroll
        for (int n = 0; n < 8; n++) {
            float2 v;
            v.x = o[n][2 * h] * inv;
            v.y = o[n][2 * h + 1] * inv;
            *reinterpret_cast<float2*>(Op + n * 8 + 2 * tig) = v;
        }
    }
}

// ---------------------------------------------------------------------------
extern "C" void kernel_launch(void* const* d_in, const int* in_sizes, int n_in,
                              void* d_out, int out_size) {
    (void)in_sizes; (void)n_in; (void)out_size;
    const float*    Q  = (const float*)d_in[0];
    const float*    K  = (const float*)d_in[1];
    const float*    V  = (const float*)d_in[2];
    const uint32_t* SC = (const uint32_t*)d_in[3];
    float*          O  = (float*)d_out;

    mask_kernel<<<NWORDS / 256, 256>>>();

    const int smem = W_TOT * (int)sizeof(uint32_t);   // 108544 B
    cudaFuncSetAttribute(attn_kernel,
                         cudaFuncAttributeMaxDynamicSharedMemorySize, smem);
    dim3 grid(S_ / 128, B_ * H_);
    attn_kernel<<<grid, 256, smem>>>(Q, K, V, SC, O);
}

// round 14
// speedup vs baseline: 1.1327x; 1.0535x over previous
#include <cuda_runtime.h>
#include <cstdint>

#define B_ 4
#define H_ 16
#define S_ 1024
#define D_ 64
#define NTOT   ((size_t)B_ * H_ * S_ * S_)
#define NWORDS (NTOT / 32)

#define KEEP_THRESH 0xE6666600u   // bits < thresh  <=>  uniform < 0.9f (verified)

__device__ uint32_t g_mask[NWORDS];             // 8 MB dropout bitmask
__device__ uint32_t g_k[B_ * H_ * S_ * D_];     // 16 MB: K bf16 hi/lo packed
__device__ uint32_t g_v[B_ * H_ * S_ * D_];     // 16 MB: V^T bf16 hi/lo packed

// g_k row (bh*1024 + key): [hi word(d-pair 0..31) | lo word 0..31]   (64 words)
// g_v row (bh*1024 + t*64 + d): [hi word(kp 0..31) | lo word 0..31]  (64 words)

// ---------------------------------------------------------------------------
// Threefry-2x32, key (0,42), JAX partitionable path (bit-exact, verified)
// ---------------------------------------------------------------------------
__device__ __forceinline__ void threefry2x32(uint32_t k0, uint32_t k1,
                                             uint32_t& x0, uint32_t& x1) {
    uint32_t ks2 = 0x1BD11BDAu ^ k0 ^ k1;
    x0 += k0; x1 += k1;
#define TF_RND(r) { x0 += x1; x1 = __funnelshift_l(x1, x1, (r)); x1 ^= x0; }
    TF_RND(13) TF_RND(15) TF_RND(26) TF_RND(6)
    x0 += k1;  x1 += ks2 + 1u;
    TF_RND(17) TF_RND(29) TF_RND(16) TF_RND(24)
    x0 += ks2; x1 += k0 + 2u;
    TF_RND(13) TF_RND(15) TF_RND(26) TF_RND(6)
    x0 += k0;  x1 += k1 + 3u;
    TF_RND(17) TF_RND(29) TF_RND(16) TF_RND(24)
    x0 += k1;  x1 += ks2 + 4u;
    TF_RND(13) TF_RND(15) TF_RND(26) TF_RND(6)
    x0 += ks2; x1 += k0 + 5u;
#undef TF_RND
}

// ---------------------------------------------------------------------------
// bf16 helpers
// ---------------------------------------------------------------------------
__device__ __forceinline__ uint32_t pack2(float lo, float hi) {
    uint32_t r;
    asm("cvt.rn.bf16x2.f32 %0, %1, %2;" : "=r"(r) : "f"(hi), "f"(lo));
    return r;
}
__device__ __forceinline__ float blo(uint32_t w) { return __uint_as_float(w << 16); }
__device__ __forceinline__ float bhi(uint32_t w) { return __uint_as_float(w & 0xffff0000u); }
__device__ __forceinline__ void split2(float a, float b, uint32_t& h, uint32_t& l) {
    h = pack2(a, b);
    l = pack2(a - blo(h), b - bhi(h));
}

// ---------------------------------------------------------------------------
// Kernel 1: dropout mask (blocks 0..8191) + K convert (8192..9215)
//           + V convert/transpose (9216..10239)
// ---------------------------------------------------------------------------
#define MASK_BLKS 8192
#define KC_BLKS   1024
#define VSTR      65           // fp32 transpose staging stride

__global__ void __launch_bounds__(256) prep_kernel(const float* __restrict__ K,
                                                   const float* __restrict__ V) {
    __shared__ float vsm[64 * VSTR];
    const int b = blockIdx.x;
    const int tid = threadIdx.x;

    if (b < MASK_BLKS) {
        // ---- threefry mask: 32 bits/thread ----
        uint32_t base = (uint32_t)(b * 256 + tid) * 32u;
        uint32_t w = 0u;
#pragma unroll 4
        for (int i = 0; i < 32; i++) {
            uint32_t x0 = 0u, x1 = base + (uint32_t)i;
            threefry2x32(0u, 42u, x0, x1);
            w |= (((x0 ^ x1) < KEEP_THRESH) ? 1u : 0u) << i;
        }
        g_mask[b * 256 + tid] = w;
    } else if (b < MASK_BLKS + KC_BLKS) {
        // ---- K convert: row-major, split hi/lo ----
        int grow = (b - MASK_BLKS) * 64 + (tid >> 2);   // global key row
        int q = tid & 3;                                 // 16-float quarter
        const float4* src = reinterpret_cast<const float4*>(K + grow * 64 + q * 16);
        uint32_t hw[8], lw[8];
#pragma unroll
        for (int i = 0; i < 4; i++) {
            float4 v = src[i];
            split2(v.x, v.y, hw[2 * i],     lw[2 * i]);
            split2(v.z, v.w, hw[2 * i + 1], lw[2 * i + 1]);
        }
        uint32_t* dst = g_k + grow * 64;
        *reinterpret_cast<uint4*>(dst + 8 * q)      = make_uint4(hw[0], hw[1], hw[2], hw[3]);
        *reinterpret_cast<uint4*>(dst + 8 * q + 4)  = make_uint4(hw[4], hw[5], hw[6], hw[7]);
        *reinterpret_cast<uint4*>(dst + 32 + 8 * q)     = make_uint4(lw[0], lw[1], lw[2], lw[3]);
        *reinterpret_cast<uint4*>(dst + 32 + 8 * q + 4) = make_uint4(lw[4], lw[5], lw[6], lw[7]);
    } else {
        // ---- V convert: transpose per 64x64 tile, split hi/lo ----
        int bb = b - MASK_BLKS - KC_BLKS;               // 0..1023 = bh*16 + t
        const float* Vt = V + (size_t)bb * 64 * 64;     // tile base (rows=keys)
        // phase 1: coalesced load into staging
#pragma unroll
        for (int i = 0; i < 4; i++) {
            int lin = tid + (i << 8);                   // 0..1023 float4 units
            int row = lin >> 4, qd = (lin & 15) << 2;
            float4 v = *reinterpret_cast<const float4*>(Vt + row * 64 + qd);
            float* d = vsm + row * VSTR + qd;
            d[0] = v.x; d[1] = v.y; d[2] = v.z; d[3] = v.w;
        }
        __syncthreads();
        // phase 2: transposed read, split, coalesced store
        int od = tid >> 2;                              // output d-row 0..63
        int kq = tid & 3;                               // kp octet 0..3
        uint32_t hw[8], lw[8];
#pragma unroll
        for (int j = 0; j < 8; j++) {
            int kp = kq * 8 + j;
            float f0 = vsm[(2 * kp) * VSTR + od];
            float f1 = vsm[(2 * kp + 1) * VSTR + od];
            split2(f0, f1, hw[j], lw[j]);
        }
        uint32_t* dst = g_v + ((size_t)bb * 64 + od) * 64;
        *reinterpret_cast<uint4*>(dst + 8 * kq)      = make_uint4(hw[0], hw[1], hw[2], hw[3]);
        *reinterpret_cast<uint4*>(dst + 8 * kq + 4)  = make_uint4(hw[4], hw[5], hw[6], hw[7]);
        *reinterpret_cast<uint4*>(dst + 32 + 8 * kq)     = make_uint4(lw[0], lw[1], lw[2], lw[3]);
        *reinterpret_cast<uint4*>(dst + 32 + 8 * kq + 4) = make_uint4(lw[4], lw[5], lw[6], lw[7]);
    }
}

// ---------------------------------------------------------------------------
// Attention kernel: double-buffered cp.async of pre-converted tiles
// ---------------------------------------------------------------------------
__device__ __forceinline__ void mma16(float d[4], const uint32_t a[4],
                                      uint32_t b0, uint32_t b1) {
    asm volatile(
        "mma.sync.aligned.m16n8k16.row.col.f32.bf16.bf16.f32 "
        "{%0,%1,%2,%3}, {%4,%5,%6,%7}, {%8,%9}, {%0,%1,%2,%3};"
        : "+f"(d[0]), "+f"(d[1]), "+f"(d[2]), "+f"(d[3])
        : "r"(a[0]), "r"(a[1]), "r"(a[2]), "r"(a[3]), "r"(b0), "r"(b1));
}
__device__ __forceinline__ void ldm_x4(uint32_t r[4], uint32_t addr) {
    asm volatile("ldmatrix.sync.aligned.m8n8.x4.shared.b16 {%0,%1,%2,%3}, [%4];"
                 : "=r"(r[0]), "=r"(r[1]), "=r"(r[2]), "=r"(r[3]) : "r"(addr));
}
__device__ __forceinline__ void cp16(uint32_t saddr, const void* g) {
    asm volatile("cp.async.cg.shared.global [%0], [%1], 16;"
                 :: "r"(saddr), "l"(g));
}

#define PW 36   // bf16x2 word stride: 144 B/row, conflict-free ldmatrix

// smem word offsets: Q + two K/V buffers (ping-pong)
#define W_QH  0
#define W_QL  (128 * PW)                 // 4608
#define W_BUF (2 * 128 * PW)             // 9216: buffers start
#define BUFW  (4 * 64 * PW)              // 9216 words per buffer
#define W_KH0 (W_BUF)
#define W_KL0 (W_BUF + 64 * PW)
#define W_VH0 (W_BUF + 2 * 64 * PW)
#define W_VL0 (W_BUF + 3 * 64 * PW)
#define W_TOT (W_BUF + 2 * BUFW)         // 27648 words = 110592 B

__global__ void __launch_bounds__(256, 2)
attn_kernel(const float* __restrict__ Q, const uint32_t* __restrict__ scale_ptr,
            float* __restrict__ O) {
    extern __shared__ uint32_t smw[];

    const int tid  = threadIdx.x;
    const int warp = tid >> 5;
    const int lane = tid & 31;
    const int gid  = lane >> 2;
    const int tig  = lane & 3;
    const int bh   = blockIdx.y;
    const int qb   = blockIdx.x << 7;
    const int r0   = warp * 16 + gid;

    uint32_t sw = *scale_ptr;
    float scale = (sw & 0x7f800000u) ? __uint_as_float(sw) : (float)(int)sw;

    const uint32_t sb = (uint32_t)__cvta_generic_to_shared(smw);
    const uint32_t laneA = (uint32_t)((lane & 15) * PW + ((lane & 16) ? 4 : 0));
    const uint32_t laneBK = (uint32_t)(((lane < 16) ? W_KH0 : W_KL0)
                                       + (lane & 7) * PW + ((lane & 8) ? 4 : 0));
    const uint32_t laneBV = (uint32_t)(((lane < 16) ? W_VH0 : W_VL0)
                                       + (lane & 7) * PW + ((lane & 8) ? 4 : 0));
    const uint32_t aQH = sb + 4u * (W_QH + (uint32_t)(warp * 16) * PW + laneA);
    const uint32_t aQL = sb + 4u * (W_QL + (uint32_t)(warp * 16) * PW + laneA);
    const uint32_t aK0 = sb + 4u * laneBK;
    const uint32_t aV0 = sb + 4u * laneBV;

    // cp.async chunk assignment: 2048 chunks (K:1024, V:1024), 8 per thread
    // lin: tensor = lin>>10, r = (lin>>4)&63, c = lin&15
    // src word off: r*64 + ((c&8)?32:0) + 4*(c&7)
    // dst: (tensor? VH/VL : KH/KL) + r*PW + 4*(c&7)
    const uint32_t kv_rowbase = (uint32_t)(bh * 1024) * 64u;

    // ---- prologue: prefetch tiles 0,1 into buffers 0,1 ----
#pragma unroll
    for (int bf = 0; bf < 2; bf++) {
        uint32_t srcb = kv_rowbase + (uint32_t)(bf * 64) * 64u;
#pragma unroll
        for (int i = 0; i < 8; i++) {
            int lin = tid + (i << 8);
            int tensor = lin >> 10;
            int r = (lin >> 4) & 63, c = lin & 15;
            uint32_t soff = srcb + (uint32_t)(r * 64 + ((c & 8) ? 32 : 0) + 4 * (c & 7));
            const uint32_t* src = (tensor ? g_v : g_k) + soff;
            uint32_t dw = (tensor ? (c < 8 ? W_VH0 : W_VL0) : (c < 8 ? W_KH0 : W_KL0))
                          + (uint32_t)(bf * BUFW + r * PW + 4 * (c & 7));
            cp16(sb + 4u * dw, src);
        }
        asm volatile("cp.async.commit_group;" ::: "memory");
    }

    // ---- Q prologue: stage scaled hi/lo bf16x2 words into smem ----
    {
        int r = tid >> 1, half = (tid & 1) * 32;
        const float4* Qp = reinterpret_cast<const float4*>(
            Q + ((size_t)bh * S_ + qb + r) * D_ + half);
        int wb = r * PW + (half >> 1);
#pragma unroll
        for (int i = 0; i < 8; i++) {
            float4 v = Qp[i];
            uint32_t h0, l0, h1, l1;
            split2(v.x * scale, v.y * scale, h0, l0);
            split2(v.z * scale, v.w * scale, h1, l1);
            smw[W_QH + wb + 2 * i]     = h0;
            smw[W_QH + wb + 2 * i + 1] = h1;
            smw[W_QL + wb + 2 * i]     = l0;
            smw[W_QL + wb + 2 * i + 1] = l1;
        }
    }

    float m_[2], l_[2];
    float o[8][4];
    m_[0] = m_[1] = -1e30f;
    l_[0] = l_[1] = 0.f;
#pragma unroll
    for (int n = 0; n < 8; n++)
#pragma unroll
        for (int c = 0; c < 4; c++) o[n][c] = 0.f;

#pragma unroll 1
    for (int t = 0; t < 16; t++) {
        // ---- prefetch dropout words (hidden under QK) ----
        uint2 mw[2];
#pragma unroll
        for (int h = 0; h < 2; h++) {
            size_t rg = (size_t)(bh * S_ + qb + r0 + 8 * h);
            mw[h] = *reinterpret_cast<const uint2*>(g_mask + (rg << 5) + t * 2);
        }

        asm volatile("cp.async.wait_group 1;" ::: "memory");
        __syncthreads();                 // tile t visible to all warps

        const uint32_t boff = (uint32_t)((t & 1) * BUFW) * 4u;
        const uint32_t aK = aK0 + boff;
        const uint32_t aV = aV0 + boff;

        // ---- QK: 3-term bf16 ----
        float s[8][4];
#pragma unroll
        for (int n = 0; n < 8; n++)
#pragma unroll
            for (int c = 0; c < 4; c++) s[n][c] = 0.f;

#pragma unroll
        for (int ks = 0; ks < 4; ks++) {
            uint32_t qh[4], ql[4];
            ldm_x4(qh, aQH + ks * 32u);
            ldm_x4(ql, aQL + ks * 32u);
#pragma unroll
            for (int n = 0; n < 8; n++) {
                uint32_t kb[4];
                ldm_x4(kb, aK + 4u * (uint32_t)(n * 8 * PW + ks * 8));
                mma16(s[n], qh, kb[0], kb[1]);
                mma16(s[n], ql, kb[0], kb[1]);
                mma16(s[n], qh, kb[2], kb[3]);
            }
        }

        // ---- online softmax ----
#pragma unroll
        for (int h = 0; h < 2; h++) {
            float mx = -1e30f;
#pragma unroll
            for (int n = 0; n < 8; n++)
                mx = fmaxf(mx, fmaxf(s[n][2 * h], s[n][2 * h + 1]));
            mx = fmaxf(mx, __shfl_xor_sync(0xffffffffu, mx, 1));
            mx = fmaxf(mx, __shfl_xor_sync(0xffffffffu, mx, 2));
            float mnew = fmaxf(m_[h], mx);
            float corr = __expf(m_[h] - mnew);
            m_[h] = mnew;
            float sum = 0.f;
#pragma unroll
            for (int n = 0; n < 8; n++) {
                float e0 = __expf(s[n][2 * h] - mnew);
                float e1 = __expf(s[n][2 * h + 1] - mnew);
                s[n][2 * h] = e0;
                s[n][2 * h + 1] = e1;
                sum += e0 + e1;
            }
            sum += __shfl_xor_sync(0xffffffffu, sum, 1);
            sum += __shfl_xor_sync(0xffffffffu, sum, 2);
            l_[h] = l_[h] * corr + sum;
#pragma unroll
            for (int n = 0; n < 8; n++) {
                o[n][2 * h] *= corr;
                o[n][2 * h + 1] *= corr;
            }
        }

        // ---- PV: dropout + pack P in regs ----
#pragma unroll
        for (int ks = 0; ks < 4; ks++) {
            uint32_t aph[4], apl[4];
#pragma unroll
            for (int q = 0; q < 4; q++) {
                int n = 2 * ks + (q >> 1);
                int h = q & 1;
                uint32_t word = (n < 4) ? mw[h].x : mw[h].y;
                int bit0 = (n & 3) * 8 + 2 * tig;
                float p0 = ((word >> bit0) & 1u) ? s[n][2 * h] : 0.f;
                float p1 = ((word >> (bit0 + 1)) & 1u) ? s[n][2 * h + 1] : 0.f;
                int ar = (q >> 1) * 2 + h;
                split2(p0, p1, aph[ar], apl[ar]);
            }
#pragma unroll
            for (int n = 0; n < 8; n++) {
                uint32_t vb[4];
                ldm_x4(vb, aV + 4u * (uint32_t)(n * 8 * PW + ks * 8));
                mma16(o[n], aph, vb[0], vb[1]);
                mma16(o[n], aph, vb[2], vb[3]);
                mma16(o[n], apl, vb[0], vb[1]);
            }
        }

        __syncthreads();                 // all warps done with buf[t&1]

        // ---- prefetch tile t+2 into buf[t&1] ----
        if (t < 14) {
            uint32_t srcb = kv_rowbase + (uint32_t)((t + 2) * 64) * 64u;
#pragma unroll
            for (int i = 0; i < 8; i++) {
                int lin = tid + (i << 8);
                int tensor = lin >> 10;
                int r = (lin >> 4) & 63, c = lin & 15;
                uint32_t soff = srcb + (uint32_t)(r * 64 + ((c & 8) ? 32 : 0) + 4 * (c & 7));
                const uint32_t* src = (tensor ? g_v : g_k) + soff;
                uint32_t dw = (tensor ? (c < 8 ? W_VH0 : W_VL0) : (c < 8 ? W_KH0 : W_KL0))
                              + (uint32_t)((t & 1) * BUFW + r * PW + 4 * (c & 7));
                cp16(sb + 4u * dw, src);
            }
        }
        asm volatile("cp.async.commit_group;" ::: "memory");   // keep 2 in flight
    }

    // ---- epilogue: O / (0.9 * l) ----
#pragma unroll
    for (int h = 0; h < 2; h++) {
        float inv = 1.f / (0.9f * l_[h]);
        int row = qb + r0 + h * 8;
        float* Op = O + ((size_t)bh * S_ + row) * D_;
#pragma unroll
        for (int n = 0; n < 8; n++) {
            float2 v;
            v.x = o[n][2 * h] * inv;
            v.y = o[n][2 * h + 1] * inv;
            *reinterpret_cast<float2*>(Op + n * 8 + 2 * tig) = v;
        }
    }
}

// ---------------------------------------------------------------------------
extern "C" void kernel_launch(void* const* d_in, const int* in_sizes, int n_in,
                              void* d_out, int out_size) {
    (void)in_sizes; (void)n_in; (void)out_size;
    const float*    Q  = (const float*)d_in[0];
    const float*    K  = (const float*)d_in[1];
    const float*    V  = (const float*)d_in[2];
    const uint32_t* SC = (const uint32_t*)d_in[3];
    float*          O  = (float*)d_out;

    prep_kernel<<<MASK_BLKS + 2 * KC_BLKS, 256>>>(K, V);

    const int smem = W_TOT * (int)sizeof(uint32_t);   // 110592 B
    cudaFuncSetAttribute(attn_kernel,
                         cudaFuncAttributeMaxDynamicSharedMemorySize, smem);
    dim3 grid(S_ / 128, B_ * H_);
    attn_kernel<<<grid, 256, smem>>>(Q, SC, O);
}